// round 3
// baseline (speedup 1.0000x reference)
#include <cuda_runtime.h>
#include <math.h>

#define B_  4
#define S_  2048
#define HID 1024
#define NH  16
#define HD  64

typedef unsigned long long u64;

// Scratch (device globals: no allocation allowed in kernel_launch).
__device__ __align__(128) float g_Q[B_ * NH * S_ * HD];
__device__ __align__(128) float g_K[B_ * NH * S_ * HD];
__device__ __align__(128) float g_V[B_ * NH * S_ * HD];
__device__ __align__(128) float g_Wt[3 * HID * HID];   // W transposed: [n][k]

// ---- packed f32x2 helpers -------------------------------------------------
__device__ __forceinline__ void ffma2(u64& acc, u64 a, u64 b) {
    asm("fma.rn.f32x2 %0, %1, %2, %0;" : "+l"(acc) : "l"(a), "l"(b));
}
__device__ __forceinline__ u64 mul2(u64 a, u64 b) {
    u64 r; asm("mul.rn.f32x2 %0, %1, %2;" : "=l"(r) : "l"(a), "l"(b)); return r;
}
__device__ __forceinline__ u64 dup2(float f) {
    u64 r; unsigned u = __float_as_uint(f);
    asm("mov.b64 %0, {%1, %1};" : "=l"(r) : "r"(u)); return r;
}
__device__ __forceinline__ float2 unpk(u64 a) {
    unsigned lo, hi;
    asm("mov.b64 {%0, %1}, %2;" : "=r"(lo), "=r"(hi) : "l"(a));
    return make_float2(__uint_as_float(lo), __uint_as_float(hi));
}
// XOR-swizzled 64-float row layout: float index of 4-float chunk start.
__device__ __forceinline__ int swz(int row, int chunk) {
    return row * 64 + ((chunk ^ ((row >> 2) & 7)) << 2);
}

// ---------------------------------------------------------------------------
// Kernel 0: transpose W -> g_Wt  (Wt[n][k] = W[k][n])
// ---------------------------------------------------------------------------
__global__ __launch_bounds__(256) void transpose_w(
    const float* __restrict__ Wq, const float* __restrict__ Wk,
    const float* __restrict__ Wv)
{
    const float* W = (blockIdx.z == 0) ? Wq : (blockIdx.z == 1) ? Wk : Wv;
    float* D = g_Wt + (size_t)blockIdx.z * HID * HID;
    __shared__ float t[32][33];
    int x0 = blockIdx.x * 32, y0 = blockIdx.y * 32;
    int tx = threadIdx.x & 31, ry = threadIdx.x >> 5;   // 32 x 8
    #pragma unroll
    for (int i = 0; i < 32; i += 8)
        t[ry + i][tx] = W[(size_t)(y0 + ry + i) * HID + x0 + tx];
    __syncthreads();
    #pragma unroll
    for (int i = 0; i < 32; i += 8)
        D[(size_t)(x0 + ry + i) * HID + y0 + tx] = t[tx][ry + i];
}

// ---------------------------------------------------------------------------
// Kernel 1: y = x @ W + b, dot-product oriented (both operands k-contiguous),
// scattered into [B, H, S, D]. 64x64 tile, 256 threads, 4x4 microtile, FFMA2.
// ---------------------------------------------------------------------------
__global__ __launch_bounds__(256, 2) void qkv_gemm(
    const float* __restrict__ x,
    const float* __restrict__ bq, const float* __restrict__ bk,
    const float* __restrict__ bv)
{
    const int z = blockIdx.z;
    const float* Wt   = g_Wt + (size_t)z * HID * HID;
    const float* bias = (z == 0) ? bq : (z == 1) ? bk : bv;
    float* dst        = (z == 0) ? g_Q : (z == 1) ? g_K : g_V;

    __shared__ __align__(16) float xs[64 * 64];
    __shared__ __align__(16) float ws[64 * 64];

    const int m0 = blockIdx.y * 64;
    const int n0 = blockIdx.x * 64;
    const int tid = threadIdx.x;
    const int tx = tid & 15;
    const int ty = tid >> 4;

    u64 acc2[4][4] = {};

    for (int k0 = 0; k0 < HID; k0 += 64) {
        #pragma unroll
        for (int i = 0; i < 4; i++) {
            int lin = tid + i * 256;
            int row = lin >> 4, c = lin & 15;
            *(float4*)&xs[swz(row, c)] =
                *(const float4*)&x[(size_t)(m0 + row) * HID + k0 + c * 4];
            *(float4*)&ws[swz(row, c)] =
                *(const float4*)&Wt[(size_t)(n0 + row) * HID + k0 + c * 4];
        }
        __syncthreads();

        #pragma unroll
        for (int c = 0; c < 16; c++) {
            ulonglong2 a[4], w[4];
            #pragma unroll
            for (int i = 0; i < 4; i++)
                a[i] = *(const ulonglong2*)&xs[swz(ty * 4 + i, c)];
            #pragma unroll
            for (int j = 0; j < 4; j++)
                w[j] = *(const ulonglong2*)&ws[swz(tx * 4 + j, c)];
            #pragma unroll
            for (int i = 0; i < 4; i++)
                #pragma unroll
                for (int j = 0; j < 4; j++) {
                    ffma2(acc2[i][j], a[i].x, w[j].x);
                    ffma2(acc2[i][j], a[i].y, w[j].y);
                }
        }
        __syncthreads();
    }

    const int h = n0 >> 6;   // 64-wide n tile == one head
    #pragma unroll
    for (int i = 0; i < 4; i++) {
        int m = m0 + ty * 4 + i;
        int b = m >> 11;
        int s = m & (S_ - 1);
        float4 r;
        float2 v0 = unpk(acc2[i][0]);
        float2 v1 = unpk(acc2[i][1]);
        float2 v2 = unpk(acc2[i][2]);
        float2 v3 = unpk(acc2[i][3]);
        r.x = v0.x + v0.y + bias[n0 + tx * 4 + 0];
        r.y = v1.x + v1.y + bias[n0 + tx * 4 + 1];
        r.z = v2.x + v2.y + bias[n0 + tx * 4 + 2];
        r.w = v3.x + v3.y + bias[n0 + tx * 4 + 3];
        *(float4*)&dst[(((size_t)b * NH + h) * S_ + s) * HD + tx * 4] = r;
    }
}

// ---------------------------------------------------------------------------
// Kernel 2: flash attention, one (b, h, 64-query tile) per block.
// 256 threads = 16x16 grid, 4x4 microtiles, all-register online softmax.
// ---------------------------------------------------------------------------
__global__ __launch_bounds__(256, 2) void attn_kernel(
    const float* __restrict__ T,
    const int*   __restrict__ mask,
    const float* __restrict__ alpha_p,
    float*       __restrict__ out)
{
    __shared__ __align__(16) float Qs[64 * 64];
    __shared__ __align__(16) float Ks[64 * 64];
    __shared__ __align__(16) float Vs[64 * 64];
    __shared__ __align__(16) float Ps[64 * 64];

    const int q0 = blockIdx.x * 64;
    const int h  = blockIdx.y;
    const int b  = blockIdx.z;
    const int tid = threadIdx.x;
    const int tx = tid & 15;
    const int ty = tid >> 4;

    const float nalpha = -fabsf(*alpha_p);
    const float* Qg = g_Q + ((size_t)b * NH + h) * S_ * HD;
    const float* Kg = g_K + ((size_t)b * NH + h) * S_ * HD;
    const float* Vg = g_V + ((size_t)b * NH + h) * S_ * HD;
    const float* Tb = T    + (size_t)b * S_ * S_;
    const int*   Mb = mask + (size_t)b * S_ * S_;

    #pragma unroll
    for (int i = 0; i < 4; i++) {
        int lin = tid + i * 256;
        int row = lin >> 4, c = lin & 15;
        *(float4*)&Qs[swz(row, c)] =
            *(const float4*)&Qg[(size_t)(q0 + row) * HD + c * 4];
    }

    float m_run[4], l_run[4];
    u64 o2[4][2];
    #pragma unroll
    for (int i = 0; i < 4; i++) {
        m_run[i] = -INFINITY; l_run[i] = 0.f;
        o2[i][0] = 0ull; o2[i][1] = 0ull;
    }

    for (int k0 = 0; k0 < S_; k0 += 64) {
        __syncthreads();   // prior-tile Ks/Vs/Ps reads complete (covers Qs load too)
        #pragma unroll
        for (int i = 0; i < 4; i++) {
            int lin = tid + i * 256;
            int row = lin >> 4, c = lin & 15;
            *(float4*)&Ks[swz(row, c)] =
                *(const float4*)&Kg[(size_t)(k0 + row) * HD + c * 4];
            *(float4*)&Vs[swz(row, c)] =
                *(const float4*)&Vg[(size_t)(k0 + row) * HD + c * 4];
        }
        __syncthreads();

        // ---- scores: 4x4 dot products over d, packed pairs ----
        u64 acc2[4][4] = {};
        #pragma unroll
        for (int c = 0; c < 16; c++) {
            ulonglong2 qa[4], kb[4];
            #pragma unroll
            for (int i = 0; i < 4; i++)
                qa[i] = *(const ulonglong2*)&Qs[swz(ty * 4 + i, c)];
            #pragma unroll
            for (int j = 0; j < 4; j++)
                kb[j] = *(const ulonglong2*)&Ks[swz(tx * 4 + j, c)];
            #pragma unroll
            for (int i = 0; i < 4; i++)
                #pragma unroll
                for (int j = 0; j < 4; j++) {
                    ffma2(acc2[i][j], qa[i].x, kb[j].x);
                    ffma2(acc2[i][j], qa[i].y, kb[j].y);
                }
        }

        // ---- bias + mask + online softmax (registers + shfl) ----
        float p[4][4];
        #pragma unroll
        for (int i = 0; i < 4; i++) {
            int qg = q0 + ty * 4 + i;
            float4 t4 = *(const float4*)&Tb[(size_t)qg * S_ + k0 + tx * 4];
            int4   m4 = *(const int4*)  &Mb[(size_t)qg * S_ + k0 + tx * 4];
            float2 u0 = unpk(acc2[i][0]);
            float2 u1 = unpk(acc2[i][1]);
            float2 u2 = unpk(acc2[i][2]);
            float2 u3 = unpk(acc2[i][3]);
            p[i][0] = (m4.x == 0) ? -1e9f : (u0.x + u0.y) * 0.125f + nalpha * t4.x;
            p[i][1] = (m4.y == 0) ? -1e9f : (u1.x + u1.y) * 0.125f + nalpha * t4.y;
            p[i][2] = (m4.z == 0) ? -1e9f : (u2.x + u2.y) * 0.125f + nalpha * t4.z;
            p[i][3] = (m4.w == 0) ? -1e9f : (u3.x + u3.y) * 0.125f + nalpha * t4.w;
        }

        #pragma unroll
        for (int i = 0; i < 4; i++) {
            float mloc = fmaxf(fmaxf(p[i][0], p[i][1]), fmaxf(p[i][2], p[i][3]));
            mloc = fmaxf(mloc, __shfl_xor_sync(0xFFFFFFFFu, mloc, 1));
            mloc = fmaxf(mloc, __shfl_xor_sync(0xFFFFFFFFu, mloc, 2));
            mloc = fmaxf(mloc, __shfl_xor_sync(0xFFFFFFFFu, mloc, 4));
            mloc = fmaxf(mloc, __shfl_xor_sync(0xFFFFFFFFu, mloc, 8));
            float mnew = fmaxf(m_run[i], mloc);
            float corr = __expf(m_run[i] - mnew);     // 0 on first tile
            float ps = 0.f;
            #pragma unroll
            for (int j = 0; j < 4; j++) {
                p[i][j] = __expf(p[i][j] - mnew);
                ps += p[i][j];
            }
            ps += __shfl_xor_sync(0xFFFFFFFFu, ps, 1);
            ps += __shfl_xor_sync(0xFFFFFFFFu, ps, 2);
            ps += __shfl_xor_sync(0xFFFFFFFFu, ps, 4);
            ps += __shfl_xor_sync(0xFFFFFFFFu, ps, 8);
            l_run[i] = l_run[i] * corr + ps;
            m_run[i] = mnew;
            u64 c2 = dup2(corr);
            o2[i][0] = mul2(o2[i][0], c2);
            o2[i][1] = mul2(o2[i][1], c2);
            *(float4*)&Ps[swz(ty * 4 + i, tx)] =
                make_float4(p[i][0], p[i][1], p[i][2], p[i][3]);
        }
        __syncwarp();   // Ps produced/consumed inside the same 16-lane groups' warp

        // ---- O += P @ V : 4q x 4d microtile, packed pairs over d ----
        #pragma unroll
        for (int kc = 0; kc < 16; kc++) {
            float4 pv[4];
            ulonglong2 vv[4];
            #pragma unroll
            for (int i = 0; i < 4; i++)
                pv[i] = *(const float4*)&Ps[swz(ty * 4 + i, kc)];
            #pragma unroll
            for (int jj = 0; jj < 4; jj++)
                vv[jj] = *(const ulonglong2*)&Vs[swz(kc * 4 + jj, tx)];
            #pragma unroll
            for (int i = 0; i < 4; i++) {
                float pe[4] = {pv[i].x, pv[i].y, pv[i].z, pv[i].w};
                #pragma unroll
                for (int jj = 0; jj < 4; jj++) {
                    u64 pd = dup2(pe[jj]);
                    ffma2(o2[i][0], pd, vv[jj].x);
                    ffma2(o2[i][1], pd, vv[jj].y);
                }
            }
        }
    }

    // ---- epilogue ----
    #pragma unroll
    for (int i = 0; i < 4; i++) {
        float inv = 1.f / l_run[i];
        float2 a = unpk(o2[i][0]);
        float2 c = unpk(o2[i][1]);
        int s = q0 + ty * 4 + i;
        *(float4*)&out[((size_t)b * S_ + s) * HID + h * HD + tx * 4] =
            make_float4(a.x * inv, a.y * inv, c.x * inv, c.y * inv);
    }
}

// ---------------------------------------------------------------------------
// Launch
// ---------------------------------------------------------------------------
extern "C" void kernel_launch(void* const* d_in, const int* in_sizes, int n_in,
                              void* d_out, int out_size)
{
    const float* x     = (const float*)d_in[0];
    const float* T     = (const float*)d_in[1];
    const int*   mask  = (const int*)  d_in[2];
    const float* Wq    = (const float*)d_in[3];
    const float* bq    = (const float*)d_in[4];
    const float* Wk    = (const float*)d_in[5];
    const float* bk    = (const float*)d_in[6];
    const float* Wv    = (const float*)d_in[7];
    const float* bv    = (const float*)d_in[8];
    const float* alpha = (const float*)d_in[9];
    float* out = (float*)d_out;

    dim3 gt(HID / 32, HID / 32, 3);
    transpose_w<<<gt, 256>>>(Wq, Wk, Wv);

    dim3 g1(HID / 64, (B_ * S_) / 64, 3);
    qkv_gemm<<<g1, 256>>>(x, bq, bk, bv);

    dim3 g2(S_ / 64, NH, B_);
    attn_kernel<<<g2, 256>>>(T, mask, alpha, out);
}

// round 4
// speedup vs baseline: 1.2843x; 1.2843x over previous
#include <cuda_runtime.h>
#include <math.h>

#define B_  4
#define S_  2048
#define HID 1024
#define NH  16
#define HD  64

typedef unsigned long long u64;

// Scratch (device globals: no allocation allowed in kernel_launch).
__device__ __align__(128) float g_Q[B_ * NH * S_ * HD];
__device__ __align__(128) float g_K[B_ * NH * S_ * HD];
__device__ __align__(128) float g_V[B_ * NH * S_ * HD];

// ---- packed f32x2 helpers -------------------------------------------------
__device__ __forceinline__ void ffma2(u64& acc, u64 a, u64 b) {
    asm("fma.rn.f32x2 %0, %1, %2, %0;" : "+l"(acc) : "l"(a), "l"(b));
}
__device__ __forceinline__ u64 mul2(u64 a, u64 b) {
    u64 r; asm("mul.rn.f32x2 %0, %1, %2;" : "=l"(r) : "l"(a), "l"(b)); return r;
}
__device__ __forceinline__ u64 dup2(float f) {
    u64 r; unsigned u = __float_as_uint(f);
    asm("mov.b64 %0, {%1, %1};" : "=l"(r) : "r"(u)); return r;
}
__device__ __forceinline__ u64 pk2(float a, float b) {
    u64 r;
    asm("mov.b64 %0, {%1, %2};" : "=l"(r)
        : "r"(__float_as_uint(a)), "r"(__float_as_uint(b)));
    return r;
}
__device__ __forceinline__ float2 unpk(u64 a) {
    unsigned lo, hi;
    asm("mov.b64 {%0, %1}, %2;" : "=r"(lo), "=r"(hi) : "l"(a));
    return make_float2(__uint_as_float(lo), __uint_as_float(hi));
}

// Thread's k-column set in the attention score tile (bank-conflict-free).
__device__ __forceinline__ int kidx(int tx, int j) {
    return 2 * tx + (j & 1) + 32 * (j >> 1);
}

// ---------------------------------------------------------------------------
// Kernel 1: y = x @ W + b  ->  [B,H,S,D].  128x128 tile, 256 threads,
// microtile 8m x 8n; FFMA2 packed along n (W is [k][n]: n-pairs are native).
// x operand is a broadcast scalar (dup2) — no transposes anywhere.
// ---------------------------------------------------------------------------
#define XP 65     // xs row pad ([m][k])
#define WP 132    // ws row pad ([k][n]), 16B-aligned rows

__global__ __launch_bounds__(256, 2) void qkv_gemm(
    const float* __restrict__ x,
    const float* __restrict__ Wq, const float* __restrict__ bq,
    const float* __restrict__ Wk, const float* __restrict__ bk,
    const float* __restrict__ Wv, const float* __restrict__ bv)
{
    extern __shared__ float smg[];
    float* xs = smg;              // 128 x XP
    float* ws = smg + 128 * XP;   // 64 x WP

    const int z = blockIdx.z;
    const float* W    = (z == 0) ? Wq : (z == 1) ? Wk : Wv;
    const float* bias = (z == 0) ? bq : (z == 1) ? bk : bv;
    float* dst        = (z == 0) ? g_Q : (z == 1) ? g_K : g_V;

    const int n0 = blockIdx.x * 128;
    const int m0 = blockIdx.y * 128;
    const int tid = threadIdx.x;
    const int tx = tid & 15;
    const int ty = tid >> 4;

    u64 acc2[8][4] = {};

    for (int k0 = 0; k0 < HID; k0 += 64) {
        __syncthreads();
        #pragma unroll
        for (int i = 0; i < 8; i++) {
            int lin = tid + i * 256;
            int r = lin >> 4, c = lin & 15;          // x: 128 rows x 16 chunks
            float4 xv = *(const float4*)&x[(size_t)(m0 + r) * HID + k0 + c * 4];
            xs[r * XP + c * 4 + 0] = xv.x;
            xs[r * XP + c * 4 + 1] = xv.y;
            xs[r * XP + c * 4 + 2] = xv.z;
            xs[r * XP + c * 4 + 3] = xv.w;
            int rw = lin >> 5, cw = lin & 31;        // W: 64 rows x 32 chunks
            float4 wv = *(const float4*)&W[(size_t)(k0 + rw) * HID + n0 + cw * 4];
            *(float4*)&ws[rw * WP + cw * 4] = wv;
        }
        __syncthreads();

        #pragma unroll 8
        for (int c = 0; c < 64; c++) {
            u64 wp[4];
            #pragma unroll
            for (int j = 0; j < 4; j++)
                wp[j] = *(const u64*)&ws[c * WP + 2 * tx + 32 * j];
            u64 xd[8];
            #pragma unroll
            for (int i = 0; i < 8; i++)
                xd[i] = dup2(xs[(ty * 8 + i) * XP + c]);
            #pragma unroll
            for (int i = 0; i < 8; i++)
                #pragma unroll
                for (int j = 0; j < 4; j++)
                    ffma2(acc2[i][j], xd[i], wp[j]);
        }
    }

    #pragma unroll
    for (int i = 0; i < 8; i++) {
        int m = m0 + ty * 8 + i;
        int b = m >> 11;
        int s = m & (S_ - 1);
        #pragma unroll
        for (int j = 0; j < 4; j++) {
            int n = n0 + 2 * tx + 32 * j;
            float2 bb = *(const float2*)&bias[n];
            float2 r = unpk(acc2[i][j]);
            r.x += bb.x; r.y += bb.y;
            int h = n >> 6, d = n & 63;
            *(float2*)&dst[(((size_t)b * NH + h) * S_ + s) * HD + d] = r;
        }
    }
}

// ---------------------------------------------------------------------------
// Kernel 2: flash attention, 128-query x 128-key tiles, 256 threads.
// Scores/outputs FFMA2-packed along q (Qt transposed once per block).
// K and V operands are broadcast scalars. grid.x = head (T/mask L2 reuse).
// ---------------------------------------------------------------------------
#define QP 130    // Qt row pad ([d][q])
#define KP 65     // Ks row pad ([k][d])
#define PP 130    // Pt row pad ([k][q])

__global__ __launch_bounds__(256, 1) void attn_kernel(
    const float* __restrict__ T,
    const int*   __restrict__ mask,
    const float* __restrict__ alpha_p,
    float*       __restrict__ out)
{
    extern __shared__ float sma[];
    float* Qt = sma;                       // 64 x QP
    float* Ks = Qt + 64 * QP;              // 128 x KP
    float* Vs = Ks + 128 * KP;             // 128 x 64
    float* Pt = Vs + 128 * 64;             // 128 x PP

    const int h  = blockIdx.x;             // head fastest: T/mask shared in L2
    const int q0 = blockIdx.y * 128;
    const int b  = blockIdx.z;
    const int tid = threadIdx.x;
    const int tx = tid & 15;
    const int ty = tid >> 4;

    const float nalpha = -fabsf(*alpha_p);
    const float* Qg = g_Q + ((size_t)b * NH + h) * S_ * HD;
    const float* Kg = g_K + ((size_t)b * NH + h) * S_ * HD;
    const float* Vg = g_V + ((size_t)b * NH + h) * S_ * HD;
    const float* Tb = T    + (size_t)b * S_ * S_;
    const int*   Mb = mask + (size_t)b * S_ * S_;

    // Q -> Qt[d][q] (transposed once per block)
    #pragma unroll
    for (int i = 0; i < 8; i++) {
        int lin = tid + i * 256;
        int q = lin >> 4, c = lin & 15;
        float4 v = *(const float4*)&Qg[(size_t)(q0 + q) * HD + c * 4];
        Qt[(c * 4 + 0) * QP + q] = v.x;
        Qt[(c * 4 + 1) * QP + q] = v.y;
        Qt[(c * 4 + 2) * QP + q] = v.z;
        Qt[(c * 4 + 3) * QP + q] = v.w;
    }

    float m_run[8], l_run[8];
    u64 o2[4][4] = {};
    #pragma unroll
    for (int r = 0; r < 8; r++) { m_run[r] = -INFINITY; l_run[r] = 0.f; }

    for (int k0 = 0; k0 < S_; k0 += 128) {
        __syncthreads();   // prior-iter Ks/Vs/Pt reads done (covers Qt on iter 0)
        #pragma unroll
        for (int i = 0; i < 8; i++) {
            int lin = tid + i * 256;
            int k = lin >> 4, c = lin & 15;
            float4 kv = *(const float4*)&Kg[(size_t)(k0 + k) * HD + c * 4];
            Ks[k * KP + c * 4 + 0] = kv.x;
            Ks[k * KP + c * 4 + 1] = kv.y;
            Ks[k * KP + c * 4 + 2] = kv.z;
            Ks[k * KP + c * 4 + 3] = kv.w;
            float4 vv = *(const float4*)&Vg[(size_t)(k0 + k) * HD + c * 4];
            *(float4*)&Vs[k * 64 + c * 4] = vv;
        }
        __syncthreads();

        // ---- scores: q-pairs (packed) x 8 k-columns, over d ----
        u64 acc2[4][8] = {};
        #pragma unroll 8
        for (int c = 0; c < 64; c++) {
            u64 qp[4];
            #pragma unroll
            for (int m = 0; m < 4; m++)
                qp[m] = *(const u64*)&Qt[c * QP + ty * 8 + 2 * m];
            u64 kd[8];
            #pragma unroll
            for (int j = 0; j < 8; j++)
                kd[j] = dup2(Ks[kidx(tx, j) * KP + c]);
            #pragma unroll
            for (int m = 0; m < 4; m++)
                #pragma unroll
                for (int j = 0; j < 8; j++)
                    ffma2(acc2[m][j], qp[m], kd[j]);
        }

        // ---- bias + mask + online softmax ----
        #pragma unroll
        for (int m = 0; m < 4; m++) {
            float2 sc[8];
            #pragma unroll
            for (int j = 0; j < 8; j++) sc[j] = unpk(acc2[m][j]);
            float corr2[2];
            #pragma unroll
            for (int e = 0; e < 2; e++) {
                int r = 2 * m + e;
                int qg = q0 + ty * 8 + r;
                float v[8];
                #pragma unroll
                for (int jj = 0; jj < 4; jj++) {
                    size_t off = (size_t)qg * S_ + k0 + 2 * tx + 32 * jj;
                    float2 t2 = *(const float2*)&Tb[off];
                    int2  mm2 = *(const int2*)  &Mb[off];
                    float s0 = e ? sc[2 * jj].y     : sc[2 * jj].x;
                    float s1 = e ? sc[2 * jj + 1].y : sc[2 * jj + 1].x;
                    v[2 * jj]     = (mm2.x == 0) ? -1e9f : s0 * 0.125f + nalpha * t2.x;
                    v[2 * jj + 1] = (mm2.y == 0) ? -1e9f : s1 * 0.125f + nalpha * t2.y;
                }
                float mloc = v[0];
                #pragma unroll
                for (int j = 1; j < 8; j++) mloc = fmaxf(mloc, v[j]);
                mloc = fmaxf(mloc, __shfl_xor_sync(0xFFFFFFFFu, mloc, 1));
                mloc = fmaxf(mloc, __shfl_xor_sync(0xFFFFFFFFu, mloc, 2));
                mloc = fmaxf(mloc, __shfl_xor_sync(0xFFFFFFFFu, mloc, 4));
                mloc = fmaxf(mloc, __shfl_xor_sync(0xFFFFFFFFu, mloc, 8));
                float mnew = fmaxf(m_run[r], mloc);
                float corr = __expf(m_run[r] - mnew);   // 0 on first tile
                float ps = 0.f;
                #pragma unroll
                for (int j = 0; j < 8; j++) {
                    v[j] = __expf(v[j] - mnew);
                    ps += v[j];
                }
                ps += __shfl_xor_sync(0xFFFFFFFFu, ps, 1);
                ps += __shfl_xor_sync(0xFFFFFFFFu, ps, 2);
                ps += __shfl_xor_sync(0xFFFFFFFFu, ps, 4);
                ps += __shfl_xor_sync(0xFFFFFFFFu, ps, 8);
                l_run[r] = l_run[r] * corr + ps;
                m_run[r] = mnew;
                corr2[e] = corr;
                #pragma unroll
                for (int j = 0; j < 8; j++)
                    Pt[kidx(tx, j) * PP + ty * 8 + r] = v[j];
            }
            u64 c2 = pk2(corr2[0], corr2[1]);
            #pragma unroll
            for (int j = 0; j < 4; j++) o2[m][j] = mul2(o2[m][j], c2);
        }
        __syncthreads();

        // ---- O += P @ V : q-pairs (packed) x 4 d-columns, over k ----
        #pragma unroll 4
        for (int k = 0; k < 128; k++) {
            u64 p2[4];
            #pragma unroll
            for (int m = 0; m < 4; m++)
                p2[m] = *(const u64*)&Pt[k * PP + ty * 8 + 2 * m];
            u64 vd[4];
            #pragma unroll
            for (int j = 0; j < 4; j++)
                vd[j] = dup2(Vs[k * 64 + tx + 16 * j]);
            #pragma unroll
            for (int m = 0; m < 4; m++)
                #pragma unroll
                for (int j = 0; j < 4; j++)
                    ffma2(o2[m][j], p2[m], vd[j]);
        }
    }

    // ---- epilogue ----
    #pragma unroll
    for (int m = 0; m < 4; m++) {
        float inv0 = 1.f / l_run[2 * m];
        float inv1 = 1.f / l_run[2 * m + 1];
        int s0 = q0 + ty * 8 + 2 * m;
        #pragma unroll
        for (int j = 0; j < 4; j++) {
            float2 ov = unpk(o2[m][j]);
            int d = h * HD + tx + 16 * j;
            out[((size_t)b * S_ + s0)     * HID + d] = ov.x * inv0;
            out[((size_t)b * S_ + s0 + 1) * HID + d] = ov.y * inv1;
        }
    }
}

// ---------------------------------------------------------------------------
// Launch
// ---------------------------------------------------------------------------
extern "C" void kernel_launch(void* const* d_in, const int* in_sizes, int n_in,
                              void* d_out, int out_size)
{
    const float* x     = (const float*)d_in[0];
    const float* T     = (const float*)d_in[1];
    const int*   mask  = (const int*)  d_in[2];
    const float* Wq    = (const float*)d_in[3];
    const float* bq    = (const float*)d_in[4];
    const float* Wk    = (const float*)d_in[5];
    const float* bk    = (const float*)d_in[6];
    const float* Wv    = (const float*)d_in[7];
    const float* bv    = (const float*)d_in[8];
    const float* alpha = (const float*)d_in[9];
    float* out = (float*)d_out;

    const int smem_g = (128 * XP + 64 * WP) * (int)sizeof(float);   // 67072
    cudaFuncSetAttribute(qkv_gemm,
                         cudaFuncAttributeMaxDynamicSharedMemorySize, smem_g);
    dim3 g1(HID / 128, (B_ * S_) / 128, 3);
    qkv_gemm<<<g1, 256, smem_g>>>(x, Wq, bq, Wk, bk, Wv, bv);

    const int smem_a = (64 * QP + 128 * KP + 128 * 64 + 128 * PP)
                       * (int)sizeof(float);                         // 165888
    cudaFuncSetAttribute(attn_kernel,
                         cudaFuncAttributeMaxDynamicSharedMemorySize, smem_a);
    dim3 g2(NH, S_ / 128, B_);
    attn_kernel<<<g2, 256, smem_a>>>(T, mask, alpha, out);
}